// round 1
// baseline (speedup 1.0000x reference)
#include <cuda_runtime.h>

#define NRES 1024
#define CM   256
#define CZ   128
#define EPSF 1e-5f

// ---------------------------------------------------------------------------
// z kernel: one warp per (i,j) row of 128 floats.
//   out[i,j,c] = (z[i,j,c]-mu)*rsqrt(var+eps)*w[c] + b[c] + T[bin(i,j)][c]
// where T[b][c] = lin_w[c*15+b] + lin_b[c], T[15][c] = lin_b[c] (no bin hit).
// ---------------------------------------------------------------------------
__global__ __launch_bounds__(256) void re_z_kernel(
    const float4* __restrict__ z4,
    const float*  __restrict__ x,
    const float*  __restrict__ ln_z_w,
    const float*  __restrict__ ln_z_b,
    const float*  __restrict__ lin_w,   // [CZ, 15]
    const float*  __restrict__ lin_b,   // [CZ]
    float4*       __restrict__ out4)
{
    __shared__ float sT[16][CZ];
    __shared__ float sw[CZ];
    __shared__ float sb[CZ];

    int tid = threadIdx.x;
    for (int idx = tid; idx < 16 * CZ; idx += 256) {
        int b = idx >> 7;
        int c = idx & (CZ - 1);
        float v = lin_b[c];
        if (b < 15) v += lin_w[c * 15 + b];
        sT[b][c] = v;
    }
    if (tid < CZ) { sw[tid] = ln_z_w[tid]; sb[tid] = ln_z_b[tid]; }
    __syncthreads();

    int lane = tid & 31;
    int row  = blockIdx.x * 8 + (tid >> 5);   // 0 .. 1048575
    int i = row >> 10;
    int j = row & (NRES - 1);

    // 128 floats per row -> 32 float4, one per lane
    float4 v = z4[(size_t)row * 32 + lane];

    float s = v.x + v.y + v.z + v.w;
    #pragma unroll
    for (int o = 16; o; o >>= 1) s += __shfl_xor_sync(0xffffffffu, s, o);
    float mu = s * (1.0f / CZ);

    float dx = v.x - mu, dy = v.y - mu, dz = v.z - mu, dw = v.w - mu;
    float s2 = dx * dx + dy * dy + dz * dz + dw * dw;
    #pragma unroll
    for (int o = 16; o; o >>= 1) s2 += __shfl_xor_sync(0xffffffffu, s2, o);
    float rs = rsqrtf(s2 * (1.0f / CZ) + EPSF);

    // squared pairwise distance (x is tiny, L1/L2 resident; broadcast loads)
    float a0 = x[3 * i + 0] - x[3 * j + 0];
    float a1 = x[3 * i + 1] - x[3 * j + 1];
    float a2 = x[3 * i + 2] - x[3 * j + 2];
    float d2 = a0 * a0 + a1 * a1 + a2 * a2;

    // count of sq_bins strictly below d2 (same fp32 boundary semantics as ref)
    int nb = 0;
    #pragma unroll
    for (int k = 0; k < 15; k++) {
        float bb = 3.25f + 1.25f * (float)k;
        bb = bb * bb;
        nb += (d2 > bb) ? 1 : 0;
    }
    int bin = 15;                 // "no bin active" -> only lin_b
    if (nb > 0) {
        if (nb == 15) {
            bin = 14;             // upper = INF
        } else {
            float bb = 3.25f + 1.25f * (float)nb;
            bb = bb * bb;
            if (d2 < bb) bin = nb - 1;   // strict: equality -> no bin
        }
    }

    int c0 = lane * 4;
    float4 o;
    o.x = dx * rs * sw[c0 + 0] + sb[c0 + 0] + sT[bin][c0 + 0];
    o.y = dy * rs * sw[c0 + 1] + sb[c0 + 1] + sT[bin][c0 + 1];
    o.z = dz * rs * sw[c0 + 2] + sb[c0 + 2] + sT[bin][c0 + 2];
    o.w = dw * rs * sw[c0 + 3] + sb[c0 + 3] + sT[bin][c0 + 3];
    out4[(size_t)row * 32 + lane] = o;
}

// ---------------------------------------------------------------------------
// m kernel: one warp per row of 256 floats (2 float4 per lane), two-pass LN.
// ---------------------------------------------------------------------------
__global__ __launch_bounds__(256) void re_m_kernel(
    const float4* __restrict__ m4,
    const float4* __restrict__ w4,
    const float4* __restrict__ b4,
    float4*       __restrict__ out4)
{
    int lane = threadIdx.x & 31;
    int row  = blockIdx.x * 8 + (threadIdx.x >> 5);  // 0..1023

    const float4* r = m4 + (size_t)row * 64;
    float4 a = r[lane];
    float4 c = r[lane + 32];

    float s = a.x + a.y + a.z + a.w + c.x + c.y + c.z + c.w;
    #pragma unroll
    for (int o = 16; o; o >>= 1) s += __shfl_xor_sync(0xffffffffu, s, o);
    float mu = s * (1.0f / CM);

    float ax = a.x - mu, ay = a.y - mu, az = a.z - mu, aw = a.w - mu;
    float cx = c.x - mu, cy = c.y - mu, cz = c.z - mu, cw = c.w - mu;
    float s2 = ax * ax + ay * ay + az * az + aw * aw
             + cx * cx + cy * cy + cz * cz + cw * cw;
    #pragma unroll
    for (int o = 16; o; o >>= 1) s2 += __shfl_xor_sync(0xffffffffu, s2, o);
    float rs = rsqrtf(s2 * (1.0f / CM) + EPSF);

    float4 wa = w4[lane],      ba = b4[lane];
    float4 wc = w4[lane + 32], bc = b4[lane + 32];

    float4 oa, oc;
    oa.x = ax * rs * wa.x + ba.x;  oa.y = ay * rs * wa.y + ba.y;
    oa.z = az * rs * wa.z + ba.z;  oa.w = aw * rs * wa.w + ba.w;
    oc.x = cx * rs * wc.x + bc.x;  oc.y = cy * rs * wc.y + bc.y;
    oc.z = cz * rs * wc.z + bc.z;  oc.w = cw * rs * wc.w + bc.w;

    out4[(size_t)row * 64 + lane]      = oa;
    out4[(size_t)row * 64 + lane + 32] = oc;
}

extern "C" void kernel_launch(void* const* d_in, const int* in_sizes, int n_in,
                              void* d_out, int out_size)
{
    const float* m      = (const float*)d_in[0];
    const float* z      = (const float*)d_in[1];
    const float* x      = (const float*)d_in[2];
    const float* ln_m_w = (const float*)d_in[3];
    const float* ln_m_b = (const float*)d_in[4];
    const float* ln_z_w = (const float*)d_in[5];
    const float* ln_z_b = (const float*)d_in[6];
    const float* lin_w  = (const float*)d_in[7];
    const float* lin_b  = (const float*)d_in[8];

    float* out_m = (float*)d_out;                      // [1024, 256]
    float* out_z = out_m + (size_t)NRES * CM;          // [1024, 1024, 128]

    // m: 1024 rows, 8 warps/block -> 128 blocks
    re_m_kernel<<<NRES / 8, 256>>>(
        (const float4*)m, (const float4*)ln_m_w, (const float4*)ln_m_b,
        (float4*)out_m);

    // z: 1024*1024 rows, 8 warps/block -> 131072 blocks
    re_z_kernel<<<(NRES * NRES) / 8, 256>>>(
        (const float4*)z, x, ln_z_w, ln_z_b, lin_w, lin_b,
        (float4*)out_z);
}

// round 2
// speedup vs baseline: 1.5998x; 1.5998x over previous
#include <cuda_runtime.h>

#define NRES 1024
#define CM   256
#define CZ   128
#define EPSF 1e-5f

// Fused distogram table: T[b][c] = lin_b[c] + ln_z_b[c] + (b<15 ? lin_w[c,b] : 0)
// bin 15 == "no bin active" row.
__device__ float g_T[16 * CZ];

__global__ void re_prep_kernel(const float* __restrict__ lin_w,
                               const float* __restrict__ lin_b,
                               const float* __restrict__ ln_z_b)
{
    int idx = blockIdx.x * 256 + threadIdx.x;   // 0..2047
    int b = idx >> 7;
    int c = idx & (CZ - 1);
    float v = lin_b[c] + ln_z_b[c];
    if (b < 15) v += lin_w[c * 15 + b];
    g_T[idx] = v;
}

// ---------------------------------------------------------------------------
// z kernel: one warp per (i,j) row of 128 floats. No shared memory.
//   out[i,j,c] = (z-mu)*rs*w[c] + T[bin][c]
// ---------------------------------------------------------------------------
__global__ __launch_bounds__(256) void re_z_kernel(
    const float4* __restrict__ z4,
    const float*  __restrict__ x,
    const float4* __restrict__ w4,     // ln_z_w as float4[32]
    float4*       __restrict__ out4)
{
    int tid  = threadIdx.x;
    int lane = tid & 31;
    int row  = blockIdx.x * 8 + (tid >> 5);   // 0 .. 1048575
    int i = row >> 10;
    int j = row & (NRES - 1);

    float4 v = z4[(size_t)row * 32 + lane];

    // one-pass moments, joint butterfly reduction
    float s1 = v.x + v.y + v.z + v.w;
    float s2 = v.x * v.x + v.y * v.y + v.z * v.z + v.w * v.w;
    #pragma unroll
    for (int o = 16; o; o >>= 1) {
        s1 += __shfl_xor_sync(0xffffffffu, s1, o);
        s2 += __shfl_xor_sync(0xffffffffu, s2, o);
    }
    float mu  = s1 * (1.0f / CZ);
    float var = s2 * (1.0f / CZ) - mu * mu;
    float rs  = rsqrtf(var + EPSF);

    // squared pairwise distance (x tiny, cache-resident, uniform per warp)
    float a0 = __ldg(&x[3 * i + 0]) - __ldg(&x[3 * j + 0]);
    float a1 = __ldg(&x[3 * i + 1]) - __ldg(&x[3 * j + 1]);
    float a2 = __ldg(&x[3 * i + 2]) - __ldg(&x[3 * j + 2]);
    float d2 = a0 * a0 + a1 * a1 + a2 * a2;

    // count of sq_bins strictly below d2 (exact fp32 boundary semantics:
    // 3.25 + 1.25k is exactly representable, squared in fp32 like the ref)
    int nb = 0;
    #pragma unroll
    for (int k = 0; k < 15; k++) {
        float bb = 3.25f + 1.25f * (float)k;
        bb = bb * bb;
        nb += (d2 > bb) ? 1 : 0;
    }
    int bin = 15;                 // no bin active -> bias-only row
    if (nb > 0) {
        if (nb == 15) {
            bin = 14;             // upper = INF
        } else {
            float bb = 3.25f + 1.25f * (float)nb;
            bb = bb * bb;
            if (d2 < bb) bin = nb - 1;   // strict: equality -> no bin
        }
    }

    const float4* T4 = reinterpret_cast<const float4*>(g_T) + bin * 32;
    float4 t = __ldg(T4 + lane);          // uniform bin per warp, L1 hit
    float4 w = __ldg(w4 + lane);          // same line for all warps, L1 hit

    float ax = rs * w.x, ay = rs * w.y, az = rs * w.z, aw = rs * w.w;
    float4 o;
    o.x = (v.x - mu) * ax + t.x;
    o.y = (v.y - mu) * ay + t.y;
    o.z = (v.z - mu) * az + t.z;
    o.w = (v.w - mu) * aw + t.w;
    out4[(size_t)row * 32 + lane] = o;
}

// ---------------------------------------------------------------------------
// m kernel: one warp per row of 256 floats (2 float4 per lane).
// ---------------------------------------------------------------------------
__global__ __launch_bounds__(256) void re_m_kernel(
    const float4* __restrict__ m4,
    const float4* __restrict__ w4,
    const float4* __restrict__ b4,
    float4*       __restrict__ out4)
{
    int lane = threadIdx.x & 31;
    int row  = blockIdx.x * 8 + (threadIdx.x >> 5);  // 0..1023

    const float4* r = m4 + (size_t)row * 64;
    float4 a = r[lane];
    float4 c = r[lane + 32];

    float s1 = a.x + a.y + a.z + a.w + c.x + c.y + c.z + c.w;
    float s2 = a.x * a.x + a.y * a.y + a.z * a.z + a.w * a.w
             + c.x * c.x + c.y * c.y + c.z * c.z + c.w * c.w;
    #pragma unroll
    for (int o = 16; o; o >>= 1) {
        s1 += __shfl_xor_sync(0xffffffffu, s1, o);
        s2 += __shfl_xor_sync(0xffffffffu, s2, o);
    }
    float mu  = s1 * (1.0f / CM);
    float var = s2 * (1.0f / CM) - mu * mu;
    float rs  = rsqrtf(var + EPSF);

    float4 wa = w4[lane],      ba = b4[lane];
    float4 wc = w4[lane + 32], bc = b4[lane + 32];

    float4 oa, oc;
    oa.x = (a.x - mu) * rs * wa.x + ba.x;  oa.y = (a.y - mu) * rs * wa.y + ba.y;
    oa.z = (a.z - mu) * rs * wa.z + ba.z;  oa.w = (a.w - mu) * rs * wa.w + ba.w;
    oc.x = (c.x - mu) * rs * wc.x + bc.x;  oc.y = (c.y - mu) * rs * wc.y + bc.y;
    oc.z = (c.z - mu) * rs * wc.z + bc.z;  oc.w = (c.w - mu) * rs * wc.w + bc.w;

    out4[(size_t)row * 64 + lane]      = oa;
    out4[(size_t)row * 64 + lane + 32] = oc;
}

extern "C" void kernel_launch(void* const* d_in, const int* in_sizes, int n_in,
                              void* d_out, int out_size)
{
    const float* m      = (const float*)d_in[0];
    const float* z      = (const float*)d_in[1];
    const float* x      = (const float*)d_in[2];
    const float* ln_m_w = (const float*)d_in[3];
    const float* ln_m_b = (const float*)d_in[4];
    const float* ln_z_w = (const float*)d_in[5];
    const float* ln_z_b = (const float*)d_in[6];
    const float* lin_w  = (const float*)d_in[7];
    const float* lin_b  = (const float*)d_in[8];

    float* out_m = (float*)d_out;                      // [1024, 256]
    float* out_z = out_m + (size_t)NRES * CM;          // [1024, 1024, 128]

    re_prep_kernel<<<8, 256>>>(lin_w, lin_b, ln_z_b);

    re_m_kernel<<<NRES / 8, 256>>>(
        (const float4*)m, (const float4*)ln_m_w, (const float4*)ln_m_b,
        (float4*)out_m);

    re_z_kernel<<<(NRES * NRES) / 8, 256>>>(
        (const float4*)z, x, (const float4*)ln_z_w,
        (float4*)out_z);
}

// round 3
// speedup vs baseline: 1.8019x; 1.1263x over previous
#include <cuda_runtime.h>

#define NRES 1024
#define CM   256
#define CZ   128
#define EPSF 1e-5f

// Fused distogram table: T[b][c] = lin_b[c] + ln_z_b[c] + (b<15 ? lin_w[c,b] : 0)
// bin 15 == "no bin active" row (bias-only).
__device__ float g_T[16 * CZ];

__device__ __forceinline__ int dist_bin(float d2)
{
    // count of sq_bins strictly below d2 (exact fp32 boundary semantics:
    // 3.25 + 1.25k is exactly representable; squared in fp32 like the ref)
    int nb = 0;
    #pragma unroll
    for (int k = 0; k < 15; k++) {
        float bb = 3.25f + 1.25f * (float)k;
        bb = bb * bb;
        nb += (d2 > bb) ? 1 : 0;
    }
    int bin = 15;                 // no bin active -> bias-only row
    if (nb > 0) {
        if (nb == 15) {
            bin = 14;             // upper = INF
        } else {
            float bb = 3.25f + 1.25f * (float)nb;
            bb = bb * bb;
            if (d2 < bb) bin = nb - 1;   // strict: equality -> no bin
        }
    }
    return bin;
}

// ---------------------------------------------------------------------------
// Fused prep + m kernel.
//   blocks 0..7     : build g_T (2048 floats)
//   blocks 8..135   : layernorm of m, one warp per row of 256 floats
// ---------------------------------------------------------------------------
__global__ __launch_bounds__(256) void re_prep_m_kernel(
    const float*  __restrict__ lin_w,
    const float*  __restrict__ lin_b,
    const float*  __restrict__ ln_z_b,
    const float4* __restrict__ m4,
    const float4* __restrict__ w4,
    const float4* __restrict__ b4,
    float4*       __restrict__ out4)
{
    if (blockIdx.x < 8) {
        int idx = blockIdx.x * 256 + threadIdx.x;   // 0..2047
        int b = idx >> 7;
        int c = idx & (CZ - 1);
        float v = lin_b[c] + ln_z_b[c];
        if (b < 15) v += lin_w[c * 15 + b];
        g_T[idx] = v;
        return;
    }

    int lane = threadIdx.x & 31;
    int row  = (blockIdx.x - 8) * 8 + (threadIdx.x >> 5);  // 0..1023

    const float4* r = m4 + (size_t)row * 64;
    float4 a = r[lane];
    float4 c = r[lane + 32];

    float s1 = a.x + a.y + a.z + a.w + c.x + c.y + c.z + c.w;
    float s2 = a.x * a.x + a.y * a.y + a.z * a.z + a.w * a.w
             + c.x * c.x + c.y * c.y + c.z * c.z + c.w * c.w;
    #pragma unroll
    for (int o = 16; o; o >>= 1) {
        s1 += __shfl_xor_sync(0xffffffffu, s1, o);
        s2 += __shfl_xor_sync(0xffffffffu, s2, o);
    }
    float mu  = s1 * (1.0f / CM);
    float var = s2 * (1.0f / CM) - mu * mu;
    float rs  = rsqrtf(var + EPSF);

    float4 wa = w4[lane],      ba = b4[lane];
    float4 wc = w4[lane + 32], bc = b4[lane + 32];

    float4 oa, oc;
    oa.x = (a.x - mu) * rs * wa.x + ba.x;  oa.y = (a.y - mu) * rs * wa.y + ba.y;
    oa.z = (a.z - mu) * rs * wa.z + ba.z;  oa.w = (a.w - mu) * rs * wa.w + ba.w;
    oc.x = (c.x - mu) * rs * wc.x + bc.x;  oc.y = (c.y - mu) * rs * wc.y + bc.y;
    oc.z = (c.z - mu) * rs * wc.z + bc.z;  oc.w = (c.w - mu) * rs * wc.w + bc.w;

    out4[(size_t)row * 64 + lane]      = oa;
    out4[(size_t)row * 64 + lane + 32] = oc;
}

// ---------------------------------------------------------------------------
// z kernel: one warp per TWO (i,j) rows of 128 floats. No shared memory.
//   out[i,j,c] = (z-mu)*rs*w[c] + T[bin][c]
// Front-batched loads (MLP=2) for DRAM latency hiding; w amortized 2x.
// ---------------------------------------------------------------------------
__global__ __launch_bounds__(512) void re_z_kernel(
    const float4* __restrict__ z4,
    const float*  __restrict__ x,
    const float4* __restrict__ w4,     // ln_z_w as float4[32]
    float4*       __restrict__ out4)
{
    int tid  = threadIdx.x;
    int lane = tid & 31;
    int r0   = blockIdx.x * 32 + (tid >> 5) * 2;   // rows r0, r0+1
    int r1   = r0 + 1;

    // front-batch both big loads
    float4 v0 = z4[(size_t)r0 * 32 + lane];
    float4 v1 = z4[(size_t)r1 * 32 + lane];
    float4 w  = __ldg(w4 + lane);                  // L1 hit, same line all warps

    // interleaved one-pass moments for both rows
    float a1 = v0.x + v0.y + v0.z + v0.w;
    float a2 = v0.x * v0.x + v0.y * v0.y + v0.z * v0.z + v0.w * v0.w;
    float b1 = v1.x + v1.y + v1.z + v1.w;
    float b2 = v1.x * v1.x + v1.y * v1.y + v1.z * v1.z + v1.w * v1.w;
    #pragma unroll
    for (int o = 16; o; o >>= 1) {
        a1 += __shfl_xor_sync(0xffffffffu, a1, o);
        a2 += __shfl_xor_sync(0xffffffffu, a2, o);
        b1 += __shfl_xor_sync(0xffffffffu, b1, o);
        b2 += __shfl_xor_sync(0xffffffffu, b2, o);
    }
    float mu0 = a1 * (1.0f / CZ);
    float rs0 = rsqrtf(a2 * (1.0f / CZ) - mu0 * mu0 + EPSF);
    float mu1 = b1 * (1.0f / CZ);
    float rs1 = rsqrtf(b2 * (1.0f / CZ) - mu1 * mu1 + EPSF);

    // distances (x tiny, cache-resident, uniform per warp)
    int i0 = r0 >> 10, j0 = r0 & (NRES - 1);
    int i1 = r1 >> 10, j1 = r1 & (NRES - 1);
    float xi0 = __ldg(&x[3 * i0 + 0]);
    float xi1 = __ldg(&x[3 * i0 + 1]);
    float xi2 = __ldg(&x[3 * i0 + 2]);
    float p0 = xi0 - __ldg(&x[3 * j0 + 0]);
    float p1 = xi1 - __ldg(&x[3 * j0 + 1]);
    float p2 = xi2 - __ldg(&x[3 * j0 + 2]);
    float q0, q1, q2;
    if (i1 == i0) {
        q0 = xi0 - __ldg(&x[3 * j1 + 0]);
        q1 = xi1 - __ldg(&x[3 * j1 + 1]);
        q2 = xi2 - __ldg(&x[3 * j1 + 2]);
    } else {
        q0 = __ldg(&x[3 * i1 + 0]) - __ldg(&x[3 * j1 + 0]);
        q1 = __ldg(&x[3 * i1 + 1]) - __ldg(&x[3 * j1 + 1]);
        q2 = __ldg(&x[3 * i1 + 2]) - __ldg(&x[3 * j1 + 2]);
    }
    int bin0 = dist_bin(p0 * p0 + p1 * p1 + p2 * p2);
    int bin1 = dist_bin(q0 * q0 + q1 * q1 + q2 * q2);

    const float4* T4 = reinterpret_cast<const float4*>(g_T);
    float4 t0 = __ldg(T4 + bin0 * 32 + lane);   // uniform bin per warp, L1 hit
    float4 t1 = __ldg(T4 + bin1 * 32 + lane);

    float w0 = rs0 * w.x, w1 = rs0 * w.y, w2 = rs0 * w.z, w3 = rs0 * w.w;
    float4 o0;
    o0.x = (v0.x - mu0) * w0 + t0.x;
    o0.y = (v0.y - mu0) * w1 + t0.y;
    o0.z = (v0.z - mu0) * w2 + t0.z;
    o0.w = (v0.w - mu0) * w3 + t0.w;
    out4[(size_t)r0 * 32 + lane] = o0;

    float u0 = rs1 * w.x, u1 = rs1 * w.y, u2 = rs1 * w.z, u3 = rs1 * w.w;
    float4 o1;
    o1.x = (v1.x - mu1) * u0 + t1.x;
    o1.y = (v1.y - mu1) * u1 + t1.y;
    o1.z = (v1.z - mu1) * u2 + t1.z;
    o1.w = (v1.w - mu1) * u3 + t1.w;
    out4[(size_t)r1 * 32 + lane] = o1;
}

extern "C" void kernel_launch(void* const* d_in, const int* in_sizes, int n_in,
                              void* d_out, int out_size)
{
    const float* m      = (const float*)d_in[0];
    const float* z      = (const float*)d_in[1];
    const float* x      = (const float*)d_in[2];
    const float* ln_m_w = (const float*)d_in[3];
    const float* ln_m_b = (const float*)d_in[4];
    const float* ln_z_w = (const float*)d_in[5];
    const float* ln_z_b = (const float*)d_in[6];
    const float* lin_w  = (const float*)d_in[7];
    const float* lin_b  = (const float*)d_in[8];

    float* out_m = (float*)d_out;                      // [1024, 256]
    float* out_z = out_m + (size_t)NRES * CM;          // [1024, 1024, 128]

    // prep (blocks 0..7) + m layernorm (blocks 8..135)
    re_prep_m_kernel<<<8 + NRES / 8, 256>>>(
        lin_w, lin_b, ln_z_b,
        (const float4*)m, (const float4*)ln_m_w, (const float4*)ln_m_b,
        (float4*)out_m);

    // z: 1024*1024 rows, 16 warps/block, 2 rows/warp -> 32768 blocks
    re_z_kernel<<<(NRES * NRES) / 32, 512>>>(
        (const float4*)z, x, (const float4*)ln_z_w,
        (float4*)out_z);
}